// round 15
// baseline (speedup 1.0000x reference)
#include <cuda_runtime.h>
#include <cuda_fp16.h>
#include <cstdint>

#define NN 100000
#define EE 1600000
#define HH 128
#define NB ((NN + 1023) / 1024)   // 98 scan tiles

// ---------------- scratch (device globals; allocation-free) ----------------
__device__ float  g_h[(size_t)NN * HH];
__device__ float  g_tmp[(size_t)NN * HH];
__device__ float  g_agg[(size_t)NN * HH];
__device__ float  g_xt[(size_t)NN * 64];    // tf32-rounded x
__device__ float  g_wt[90112];              // tf32-rounded weights
__device__ __half g_x16[(size_t)NN * 64];   // fp16 gather copies
__device__ __half g_h16[(size_t)NN * HH];
__device__ __half g_t16[(size_t)NN * HH];
__device__ float  g_deginv[NN];
__device__ int    g_deg[NN];
__device__ int    g_rank[EE];               // edge slot within its dst row
__device__ int    g_rowptr[NN + 1];
__device__ int    g_bsum[NB];
__device__ int    g_csr[EE];
__device__ float  g_zl[NN];
__device__ float  g_zr[NN];

// weight offsets in g_wt
#define W_RES 0
#define W_L1  8192
#define W_R1  16384
#define W_L2  24576
#define W_R2  40960
#define W_L3  57344
#define W_R3  73728

// ---------------- helpers ----------------
__device__ __forceinline__ float tf32f(float x) {
    uint32_t r;
    asm("cvt.rna.tf32.f32 %0, %1;" : "=r"(r) : "f"(x));
    return __uint_as_float(r);
}
__device__ __forceinline__ uint32_t smem_u32(const void* p) {
    uint32_t a;
    asm("{ .reg .u64 t; cvta.to.shared.u64 t, %1; cvt.u32.u64 %0, t; }" : "=r"(a) : "l"(p));
    return a;
}
__device__ __forceinline__ void cp16(void* dst, const void* src, bool valid) {
    uint32_t d = smem_u32(dst);
    int sz = valid ? 16 : 0;
    asm volatile("cp.async.cg.shared.global [%0], [%1], 16, %2;"
                 :: "r"(d), "l"(src), "r"(sz) : "memory");
}

// ---------------- fused conv + degree histogram (rank-producing) ----------------
// edge_index is int32 (JAX x64 disabled => jnp.int64 silently becomes int32)
__global__ void k_conv_count(const float* __restrict__ x, const int* __restrict__ ei,
                             const float* __restrict__ Wres, const float* __restrict__ Wl1,
                             const float* __restrict__ Wr1,  const float* __restrict__ Wl2,
                             const float* __restrict__ Wr2,  const float* __restrict__ Wl3,
                             const float* __restrict__ Wr3, int convBlocks) {
    if (blockIdx.x < (unsigned)convBlocks) {
        int i = blockIdx.x * 256 + threadIdx.x;
        const int NX = NN * 64;
        if (i < NX) {
            float v = x[i];
            g_xt[i] = tf32f(v);
            g_x16[i] = __float2half_rn(v);
            return;
        }
        int j = i - NX;
        if      (j < 8192)  g_wt[j] = tf32f(Wres[j]);
        else if (j < 16384) g_wt[j] = tf32f(Wl1[j - 8192]);
        else if (j < 24576) g_wt[j] = tf32f(Wr1[j - 16384]);
        else if (j < 40960) g_wt[j] = tf32f(Wl2[j - 24576]);
        else if (j < 57344) g_wt[j] = tf32f(Wr2[j - 40960]);
        else if (j < 73728) g_wt[j] = tf32f(Wl3[j - 57344]);
        else if (j < 90112) g_wt[j] = tf32f(Wr3[j - 73728]);
    } else {
        int e = (blockIdx.x - convBlocks) * 256 + threadIdx.x;
        if (e >= EE) return;
        int d = ei[EE + e];
        d = min(max(d, 0), NN - 1);
        g_rank[e] = atomicAdd(&g_deg[d], 1);   // slot within row d
    }
}

// pass 1: per-tile (1024) exclusive scan; tile totals; deginv; re-zero deg
__global__ __launch_bounds__(1024) void k_scan1() {
    __shared__ int wsum[32];
    int t = threadIdx.x;
    int lane = t & 31, w = t >> 5;
    int i = blockIdx.x * 1024 + t;
    int v = (i < NN) ? g_deg[i] : 0;
    int x = v;
    #pragma unroll
    for (int d = 1; d < 32; d <<= 1) {
        int y = __shfl_up_sync(0xffffffffu, x, d);
        if (lane >= d) x += y;
    }
    if (lane == 31) wsum[w] = x;
    __syncthreads();
    if (w == 0) {
        int s = wsum[lane];
        #pragma unroll
        for (int d = 1; d < 32; d <<= 1) {
            int y = __shfl_up_sync(0xffffffffu, s, d);
            if (lane >= d) s += y;
        }
        wsum[lane] = s;
    }
    __syncthreads();
    int incl = x + (w > 0 ? wsum[w - 1] : 0);
    if (i < NN) {
        g_rowptr[i] = incl - v;
        g_deginv[i] = 1.0f / fmaxf((float)v, 1.0f);
        g_deg[i] = 0;
    }
    if (t == 1023) g_bsum[blockIdx.x] = incl;
}

// pass 2 (merged): each block adds sum of preceding tile totals
__global__ __launch_bounds__(1024) void k_scan3() {
    __shared__ int ssum[32];
    int t = threadIdx.x;
    int lane = t & 31, w = t >> 5;
    int v = (t < blockIdx.x) ? g_bsum[t] : 0;
    #pragma unroll
    for (int d = 16; d; d >>= 1) v += __shfl_xor_sync(0xffffffffu, v, d);
    if (lane == 0) ssum[w] = v;
    __syncthreads();
    if (w == 0) {
        int s = ssum[lane];
        #pragma unroll
        for (int d = 16; d; d >>= 1) s += __shfl_xor_sync(0xffffffffu, s, d);
        if (lane == 0) ssum[0] = s;
    }
    __syncthreads();
    int off = ssum[0];
    int i = blockIdx.x * 1024 + t;
    if (i < NN) g_rowptr[i] += off;
    if (blockIdx.x == 0 && t == 0) g_rowptr[NN] = EE;
}

// atomic-free fill using precomputed ranks
__global__ void k_fill(const int* __restrict__ ei) {
    int e = blockIdx.x * blockDim.x + threadIdx.x;
    if (e >= EE) return;
    int s = ei[e];
    int d = ei[EE + e];
    s = min(max(s, 0), NN - 1);
    d = min(max(d, 0), NN - 1);
    g_csr[g_rowptr[d] + g_rank[e]] = s;
}

// ---------------- aggregation: warp per dst node, fp16 gather, 8-way MLP ----------------
template <int F>
__global__ __launch_bounds__(256) void agg_kernel(const __half* __restrict__ in,
                                                  float* __restrict__ out) {
    int warp = (blockIdx.x * blockDim.x + threadIdx.x) >> 5;
    int lane = threadIdx.x & 31;
    if (warp >= NN) return;
    int s = g_rowptr[warp], e = g_rowptr[warp + 1];
    float dinv = g_deginv[warp];
    if (F == 128) {
        float a0 = 0.f, a1 = 0.f, a2 = 0.f, a3 = 0.f;
        int j = s;
        for (; j + 8 <= e; j += 8) {
            int i0 = g_csr[j],     i1 = g_csr[j + 1], i2 = g_csr[j + 2], i3 = g_csr[j + 3];
            int i4 = g_csr[j + 4], i5 = g_csr[j + 5], i6 = g_csr[j + 6], i7 = g_csr[j + 7];
            uint2 v0 = __ldg((const uint2*)(in + (size_t)i0 * 128) + lane);
            uint2 v1 = __ldg((const uint2*)(in + (size_t)i1 * 128) + lane);
            uint2 v2 = __ldg((const uint2*)(in + (size_t)i2 * 128) + lane);
            uint2 v3 = __ldg((const uint2*)(in + (size_t)i3 * 128) + lane);
            uint2 v4 = __ldg((const uint2*)(in + (size_t)i4 * 128) + lane);
            uint2 v5 = __ldg((const uint2*)(in + (size_t)i5 * 128) + lane);
            uint2 v6 = __ldg((const uint2*)(in + (size_t)i6 * 128) + lane);
            uint2 v7 = __ldg((const uint2*)(in + (size_t)i7 * 128) + lane);
            float2 f;
            f = __half22float2(*(__half2*)&v0.x); a0 += f.x; a1 += f.y;
            f = __half22float2(*(__half2*)&v0.y); a2 += f.x; a3 += f.y;
            f = __half22float2(*(__half2*)&v1.x); a0 += f.x; a1 += f.y;
            f = __half22float2(*(__half2*)&v1.y); a2 += f.x; a3 += f.y;
            f = __half22float2(*(__half2*)&v2.x); a0 += f.x; a1 += f.y;
            f = __half22float2(*(__half2*)&v2.y); a2 += f.x; a3 += f.y;
            f = __half22float2(*(__half2*)&v3.x); a0 += f.x; a1 += f.y;
            f = __half22float2(*(__half2*)&v3.y); a2 += f.x; a3 += f.y;
            f = __half22float2(*(__half2*)&v4.x); a0 += f.x; a1 += f.y;
            f = __half22float2(*(__half2*)&v4.y); a2 += f.x; a3 += f.y;
            f = __half22float2(*(__half2*)&v5.x); a0 += f.x; a1 += f.y;
            f = __half22float2(*(__half2*)&v5.y); a2 += f.x; a3 += f.y;
            f = __half22float2(*(__half2*)&v6.x); a0 += f.x; a1 += f.y;
            f = __half22float2(*(__half2*)&v6.y); a2 += f.x; a3 += f.y;
            f = __half22float2(*(__half2*)&v7.x); a0 += f.x; a1 += f.y;
            f = __half22float2(*(__half2*)&v7.y); a2 += f.x; a3 += f.y;
        }
        #pragma unroll
        for (int k = 0; k < 7; k++) {
            if (j + k < e) {
                int src = g_csr[j + k];
                uint2 v = __ldg((const uint2*)(in + (size_t)src * 128) + lane);
                float2 f;
                f = __half22float2(*(__half2*)&v.x); a0 += f.x; a1 += f.y;
                f = __half22float2(*(__half2*)&v.y); a2 += f.x; a3 += f.y;
            }
        }
        float4 o;
        o.x = tf32f(a0 * dinv); o.y = tf32f(a1 * dinv);
        o.z = tf32f(a2 * dinv); o.w = tf32f(a3 * dinv);
        ((float4*)(out + (size_t)warp * 128))[lane] = o;
    } else {  // F == 64
        float a0 = 0.f, a1 = 0.f;
        int j = s;
        for (; j + 8 <= e; j += 8) {
            int i0 = g_csr[j],     i1 = g_csr[j + 1], i2 = g_csr[j + 2], i3 = g_csr[j + 3];
            int i4 = g_csr[j + 4], i5 = g_csr[j + 5], i6 = g_csr[j + 6], i7 = g_csr[j + 7];
            uint32_t v0 = __ldg((const uint32_t*)(in + (size_t)i0 * 64) + lane);
            uint32_t v1 = __ldg((const uint32_t*)(in + (size_t)i1 * 64) + lane);
            uint32_t v2 = __ldg((const uint32_t*)(in + (size_t)i2 * 64) + lane);
            uint32_t v3 = __ldg((const uint32_t*)(in + (size_t)i3 * 64) + lane);
            uint32_t v4 = __ldg((const uint32_t*)(in + (size_t)i4 * 64) + lane);
            uint32_t v5 = __ldg((const uint32_t*)(in + (size_t)i5 * 64) + lane);
            uint32_t v6 = __ldg((const uint32_t*)(in + (size_t)i6 * 64) + lane);
            uint32_t v7 = __ldg((const uint32_t*)(in + (size_t)i7 * 64) + lane);
            float2 f;
            f = __half22float2(*(__half2*)&v0); a0 += f.x; a1 += f.y;
            f = __half22float2(*(__half2*)&v1); a0 += f.x; a1 += f.y;
            f = __half22float2(*(__half2*)&v2); a0 += f.x; a1 += f.y;
            f = __half22float2(*(__half2*)&v3); a0 += f.x; a1 += f.y;
            f = __half22float2(*(__half2*)&v4); a0 += f.x; a1 += f.y;
            f = __half22float2(*(__half2*)&v5); a0 += f.x; a1 += f.y;
            f = __half22float2(*(__half2*)&v6); a0 += f.x; a1 += f.y;
            f = __half22float2(*(__half2*)&v7); a0 += f.x; a1 += f.y;
        }
        #pragma unroll
        for (int k = 0; k < 7; k++) {
            if (j + k < e) {
                int src = g_csr[j + k];
                uint32_t v = __ldg((const uint32_t*)(in + (size_t)src * 64) + lane);
                float2 f = __half22float2(*(__half2*)&v);
                a0 += f.x; a1 += f.y;
            }
        }
        float2 o; o.x = tf32f(a0 * dinv); o.y = tf32f(a1 * dinv);
        ((float2*)(out + (size_t)warp * 64))[lane] = o;
    }
}

// ---------------- tf32 mma.sync GEMM, cp.async 3-stage pipeline, dual-input fused ----------------
// EPI: 0 = plain; 1 = LN-residual (+C16); 2 = projection to zl/zr
#define SA_STRIDE 36
#define SB_STRIDE 136
#define STAGEF (128 * SA_STRIDE + 32 * SB_STRIDE)   // 8960 floats per stage
#define GSMEM (3 * STAGEF * 4)                       // 107520 bytes

__device__ __forceinline__ void load_tiles(float* stage,
                                           const float* __restrict__ A,
                                           const float* __restrict__ W,
                                           int kk, int K, int row0, int tid) {
    float* sA = stage;
    float* sB = stage + 128 * SA_STRIDE;
    #pragma unroll
    for (int it = 0; it < 4; it++) {
        int idx = tid + it * 256;
        int r = idx >> 3, c4 = idx & 7;
        int gr = row0 + r;
        cp16(&sA[r * SA_STRIDE + c4 * 4], &A[(size_t)gr * K + kk + c4 * 4], gr < NN);
    }
    #pragma unroll
    for (int it = 0; it < 4; it++) {
        int idx = tid + it * 256;
        int kr = idx >> 5, n4 = idx & 31;
        cp16(&sB[kr * SB_STRIDE + n4 * 4], &W[(size_t)(kk + kr) * 128 + n4 * 4], true);
    }
    asm volatile("cp.async.commit_group;" ::: "memory");
}

template <int EPI>
__global__ __launch_bounds__(256, 2) void gemm_tc(
    const float* __restrict__ A1, const float* __restrict__ W1,
    const float* __restrict__ A2, const float* __restrict__ W2,
    const float* __restrict__ bias, float* __restrict__ C,
    __half* __restrict__ C16,
    int K, int dual, int relu, int cvtout,
    const float* __restrict__ q1, const float* __restrict__ q2)
{
    extern __shared__ float smem[];

    int tid = threadIdx.x;
    int wid = tid >> 5, lane = tid & 31;
    int g = lane >> 2, t = lane & 3;
    int row0 = blockIdx.x * 128;
    int mrow = (wid & 3) * 32;
    int ncol = (wid >> 2) * 64;
    int half = wid >> 2;

    float acc[2][8][4];
    #pragma unroll
    for (int mi = 0; mi < 2; mi++)
        #pragma unroll
        for (int nj = 0; nj < 8; nj++)
            #pragma unroll
            for (int q = 0; q < 4; q++) acc[mi][nj][q] = 0.f;

    int KT = dual ? 2 * K : K;
    int niter = KT >> 5;

    load_tiles(smem, A1, W1, 0, K, row0, tid);
    if (niter > 1) {
        const float* A = A1;
        const float* W = W1;
        int kk = 32;
        if (kk >= K) { A = A2; W = W2; kk -= K; }
        load_tiles(smem + STAGEF, A, W, kk, K, row0, tid);
    }

    int stage = 0;
    for (int itn = 0; itn < niter; itn++) {
        if (itn + 1 < niter)
            asm volatile("cp.async.wait_group 1;" ::: "memory");
        else
            asm volatile("cp.async.wait_group 0;" ::: "memory");
        __syncthreads();

        int pf = itn + 2;
        if (pf < niter) {
            int k0 = pf * 32;
            const float* A = A1;
            const float* W = W1;
            int kk = k0;
            if (k0 >= K) { A = A2; W = W2; kk = k0 - K; }
            int pstage = stage + 2; if (pstage >= 3) pstage -= 3;
            load_tiles(smem + pstage * STAGEF, A, W, kk, K, row0, tid);
        }

        const uint32_t* sA = (const uint32_t*)(smem + stage * STAGEF);
        const uint32_t* sB = sA + 128 * SA_STRIDE;

        #pragma unroll
        for (int ks = 0; ks < 4; ks++) {
            int k = ks * 8;
            uint32_t af[2][4];
            #pragma unroll
            for (int mi = 0; mi < 2; mi++) {
                int br = mrow + mi * 16;
                af[mi][0] = sA[(br + g) * SA_STRIDE + k + t];
                af[mi][1] = sA[(br + g + 8) * SA_STRIDE + k + t];
                af[mi][2] = sA[(br + g) * SA_STRIDE + k + t + 4];
                af[mi][3] = sA[(br + g + 8) * SA_STRIDE + k + t + 4];
            }
            uint32_t bf[8][2];
            #pragma unroll
            for (int nj = 0; nj < 8; nj++) {
                int col = ncol + nj * 8 + g;
                bf[nj][0] = sB[(k + t) * SB_STRIDE + col];
                bf[nj][1] = sB[(k + t + 4) * SB_STRIDE + col];
            }
            #pragma unroll
            for (int mi = 0; mi < 2; mi++)
                #pragma unroll
                for (int nj = 0; nj < 8; nj++) {
                    asm volatile(
                        "mma.sync.aligned.m16n8k8.row.col.f32.tf32.tf32.f32 "
                        "{%0,%1,%2,%3}, {%4,%5,%6,%7}, {%8,%9}, {%0,%1,%2,%3};"
                        : "+f"(acc[mi][nj][0]), "+f"(acc[mi][nj][1]),
                          "+f"(acc[mi][nj][2]), "+f"(acc[mi][nj][3])
                        : "r"(af[mi][0]), "r"(af[mi][1]), "r"(af[mi][2]), "r"(af[mi][3]),
                          "r"(bf[nj][0]), "r"(bf[nj][1]));
                }
        }
        if (++stage == 3) stage = 0;
    }

    float bv0[8], bv1[8];
    #pragma unroll
    for (int nj = 0; nj < 8; nj++) {
        int col = ncol + nj * 8 + 2 * t;
        bv0[nj] = bias[col]; bv1[nj] = bias[col + 1];
    }

    if (EPI == 0) {
        #pragma unroll
        for (int mi = 0; mi < 2; mi++) {
            int r_lo = row0 + mrow + mi * 16 + g;
            int r_hi = r_lo + 8;
            #pragma unroll
            for (int nj = 0; nj < 8; nj++) {
                int col = ncol + nj * 8 + 2 * t;
                float2 v0, v1;
                v0.x = acc[mi][nj][0] + bv0[nj]; v0.y = acc[mi][nj][1] + bv1[nj];
                v1.x = acc[mi][nj][2] + bv0[nj]; v1.y = acc[mi][nj][3] + bv1[nj];
                if (relu) {
                    v0.x = fmaxf(v0.x, 0.f); v0.y = fmaxf(v0.y, 0.f);
                    v1.x = fmaxf(v1.x, 0.f); v1.y = fmaxf(v1.y, 0.f);
                }
                if (cvtout) {
                    v0.x = tf32f(v0.x); v0.y = tf32f(v0.y);
                    v1.x = tf32f(v1.x); v1.y = tf32f(v1.y);
                }
                if (r_lo < NN) {
                    *(float2*)&C[(size_t)r_lo * 128 + col] = v0;
                    if (C16) *(__half2*)&C16[(size_t)r_lo * 128 + col] = __float22half2_rn(v0);
                }
                if (r_hi < NN) {
                    *(float2*)&C[(size_t)r_hi * 128 + col] = v1;
                    if (C16) *(__half2*)&C16[(size_t)r_hi * 128 + col] = __float22half2_rn(v1);
                }
            }
        }
    } else if (EPI == 1) {
        float S[4] = {0.f, 0.f, 0.f, 0.f}, Q[4] = {0.f, 0.f, 0.f, 0.f};
        #pragma unroll
        for (int mi = 0; mi < 2; mi++)
            #pragma unroll
            for (int nj = 0; nj < 8; nj++) {
                float a0 = acc[mi][nj][0] + bv0[nj], a1 = acc[mi][nj][1] + bv1[nj];
                float a2 = acc[mi][nj][2] + bv0[nj], a3 = acc[mi][nj][3] + bv1[nj];
                S[mi * 2]     += a0 + a1; Q[mi * 2]     += a0 * a0 + a1 * a1;
                S[mi * 2 + 1] += a2 + a3; Q[mi * 2 + 1] += a2 * a2 + a3 * a3;
            }
        #pragma unroll
        for (int ri = 0; ri < 4; ri++) {
            S[ri] += __shfl_xor_sync(0xffffffffu, S[ri], 1);
            S[ri] += __shfl_xor_sync(0xffffffffu, S[ri], 2);
            Q[ri] += __shfl_xor_sync(0xffffffffu, Q[ri], 1);
            Q[ri] += __shfl_xor_sync(0xffffffffu, Q[ri], 2);
        }
        float2* red = (float2*)smem;
        __syncthreads();
        if (t == 0) {
            #pragma unroll
            for (int ri = 0; ri < 4; ri++) {
                int row = mrow + (ri >> 1) * 16 + g + (ri & 1) * 8;
                red[row * 2 + half] = make_float2(S[ri], Q[ri]);
            }
        }
        __syncthreads();
        float mu[4], rs[4];
        #pragma unroll
        for (int ri = 0; ri < 4; ri++) {
            int row = mrow + (ri >> 1) * 16 + g + (ri & 1) * 8;
            float2 p0 = red[row * 2], p1 = red[row * 2 + 1];
            float Sf = p0.x + p1.x, Qf = p0.y + p1.y;
            mu[ri] = Sf * (1.0f / 128.0f);
            float var = Qf * (1.0f / 128.0f) - mu[ri] * mu[ri];
            rs[ri] = rsqrtf(var + 1e-5f);
        }
        #pragma unroll
        for (int mi = 0; mi < 2; mi++) {
            int r_lo = row0 + mrow + mi * 16 + g;
            int r_hi = r_lo + 8;
            #pragma unroll
            for (int nj = 0; nj < 8; nj++) {
                int col = ncol + nj * 8 + 2 * t;
                float g0 = q1[col], g1 = q1[col + 1];
                float e0 = q2[col], e1 = q2[col + 1];
                if (r_lo < NN) {
                    float a0 = acc[mi][nj][0] + bv0[nj], a1 = acc[mi][nj][1] + bv1[nj];
                    float o0 = fmaxf((a0 - mu[mi * 2]) * rs[mi * 2] * g0 + e0, 0.f);
                    float o1 = fmaxf((a1 - mu[mi * 2]) * rs[mi * 2] * g1 + e1, 0.f);
                    float2 hv = *(float2*)&C[(size_t)r_lo * 128 + col];
                    hv.x = tf32f(hv.x + o0); hv.y = tf32f(hv.y + o1);
                    *(float2*)&C[(size_t)r_lo * 128 + col] = hv;
                    *(__half2*)&C16[(size_t)r_lo * 128 + col] = __float22half2_rn(hv);
                }
                if (r_hi < NN) {
                    float a2 = acc[mi][nj][2] + bv0[nj], a3 = acc[mi][nj][3] + bv1[nj];
                    float o2 = fmaxf((a2 - mu[mi * 2 + 1]) * rs[mi * 2 + 1] * g0 + e0, 0.f);
                    float o3 = fmaxf((a3 - mu[mi * 2 + 1]) * rs[mi * 2 + 1] * g1 + e1, 0.f);
                    float2 hv = *(float2*)&C[(size_t)r_hi * 128 + col];
                    hv.x = tf32f(hv.x + o2); hv.y = tf32f(hv.y + o3);
                    *(float2*)&C[(size_t)r_hi * 128 + col] = hv;
                    *(__half2*)&C16[(size_t)r_hi * 128 + col] = __float22half2_rn(hv);
                }
            }
        }
    } else {
        float sl[4] = {0.f, 0.f, 0.f, 0.f}, sr[4] = {0.f, 0.f, 0.f, 0.f};
        #pragma unroll
        for (int nj = 0; nj < 8; nj++) {
            int col = ncol + nj * 8 + 2 * t;
            float wl0 = __ldg(&q1[col]), wl1 = __ldg(&q1[col + 1]);
            float wr0 = __ldg(&q2[col]), wr1 = __ldg(&q2[col + 1]);
            #pragma unroll
            for (int mi = 0; mi < 2; mi++) {
                float a0 = fmaxf(acc[mi][nj][0] + bv0[nj], 0.f);
                float a1 = fmaxf(acc[mi][nj][1] + bv1[nj], 0.f);
                float a2 = fmaxf(acc[mi][nj][2] + bv0[nj], 0.f);
                float a3 = fmaxf(acc[mi][nj][3] + bv1[nj], 0.f);
                sl[mi * 2]     += a0 * wl0 + a1 * wl1;
                sr[mi * 2]     += a0 * wr0 + a1 * wr1;
                sl[mi * 2 + 1] += a2 * wl0 + a3 * wl1;
                sr[mi * 2 + 1] += a2 * wr0 + a3 * wr1;
            }
        }
        #pragma unroll
        for (int ri = 0; ri < 4; ri++) {
            sl[ri] += __shfl_xor_sync(0xffffffffu, sl[ri], 1);
            sl[ri] += __shfl_xor_sync(0xffffffffu, sl[ri], 2);
            sr[ri] += __shfl_xor_sync(0xffffffffu, sr[ri], 1);
            sr[ri] += __shfl_xor_sync(0xffffffffu, sr[ri], 2);
        }
        float2* red = (float2*)smem;
        __syncthreads();
        if (t == 0) {
            #pragma unroll
            for (int ri = 0; ri < 4; ri++) {
                int row = mrow + (ri >> 1) * 16 + g + (ri & 1) * 8;
                red[row * 2 + half] = make_float2(sl[ri], sr[ri]);
            }
        }
        __syncthreads();
        if (t == 0 && half == 0) {
            #pragma unroll
            for (int ri = 0; ri < 4; ri++) {
                int row = mrow + (ri >> 1) * 16 + g + (ri & 1) * 8;
                int gr = row0 + row;
                if (gr < NN) {
                    float2 p0 = red[row * 2], p1 = red[row * 2 + 1];
                    g_zl[gr] = p0.x + p1.x;
                    g_zr[gr] = p0.y + p1.y;
                }
            }
        }
    }
}

// ---------------- final: out = zr + b4 + deginv * sum(zl[neighbors]) ----------------
__global__ void final_kernel(const float* __restrict__ b4, float* __restrict__ out) {
    int i = blockIdx.x * blockDim.x + threadIdx.x;
    if (i >= NN) return;
    int s = g_rowptr[i], e = g_rowptr[i + 1];
    float sum = 0.f;
    int j = s;
    for (; j + 4 <= e; j += 4) {
        float z0 = __ldg(&g_zl[g_csr[j]]);
        float z1 = __ldg(&g_zl[g_csr[j + 1]]);
        float z2 = __ldg(&g_zl[g_csr[j + 2]]);
        float z3 = __ldg(&g_zl[g_csr[j + 3]]);
        sum += (z0 + z1) + (z2 + z3);
    }
    for (; j < e; j++) sum += __ldg(&g_zl[g_csr[j]]);
    out[i] = g_zr[i] + b4[0] + g_deginv[i] * sum;
}

// ---------------- host ----------------
template <typename T>
static T* sym(const void* s) {
    void* p = nullptr;
    cudaGetSymbolAddress(&p, s);
    return (T*)p;
}

extern "C" void kernel_launch(void* const* d_in, const int* in_sizes, int n_in,
                              void* d_out, int out_size) {
    const float* x    = (const float*)d_in[0];
    const int*   ei   = (const int*)d_in[1];     // int32 (JAX x64 disabled)
    const float* Wl1  = (const float*)d_in[2];
    const float* Wr1  = (const float*)d_in[3];
    const float* b1   = (const float*)d_in[4];
    const float* ln_g = (const float*)d_in[5];
    const float* ln_b = (const float*)d_in[6];
    const float* Wres = (const float*)d_in[7];
    const float* bres = (const float*)d_in[8];
    const float* Wl2  = (const float*)d_in[9];
    const float* Wr2  = (const float*)d_in[10];
    const float* b2   = (const float*)d_in[11];
    const float* Wl3  = (const float*)d_in[12];
    const float* Wr3  = (const float*)d_in[13];
    const float* b3   = (const float*)d_in[14];
    const float* Wl4  = (const float*)d_in[15];
    const float* Wr4  = (const float*)d_in[16];
    const float* b4   = (const float*)d_in[17];
    float* out = (float*)d_out;

    float*  hp   = sym<float>(g_h);
    float*  tmpp = sym<float>(g_tmp);
    float*  aggp = sym<float>(g_agg);
    float*  xt   = sym<float>(g_xt);
    float*  wt   = sym<float>(g_wt);
    __half* x16  = sym<__half>(g_x16);
    __half* h16  = sym<__half>(g_h16);
    __half* t16  = sym<__half>(g_t16);

    // one-time stream/event setup (first call is the uncaptured correctness run)
    static cudaStream_t s_side = nullptr;
    static cudaEvent_t ev_fork = nullptr, ev_join = nullptr;
    if (!s_side) {
        cudaStreamCreateWithFlags(&s_side, cudaStreamNonBlocking);
        cudaEventCreateWithFlags(&ev_fork, cudaEventDisableTiming);
        cudaEventCreateWithFlags(&ev_join, cudaEventDisableTiming);
        cudaFuncSetAttribute(gemm_tc<0>, cudaFuncAttributeMaxDynamicSharedMemorySize, GSMEM);
        cudaFuncSetAttribute(gemm_tc<1>, cudaFuncAttributeMaxDynamicSharedMemorySize, GSMEM);
        cudaFuncSetAttribute(gemm_tc<2>, cudaFuncAttributeMaxDynamicSharedMemorySize, GSMEM);
    }

    const int warpBlocks = (NN + 7) / 8;          // 12500
    const int gemmBlocks = (NN + 127) / 128;      // 782
    const int edgeBlocks = (EE + 255) / 256;
    const int nodeBlocks = (NN + 255) / 256;
    const int convBlocks = (NN * 64 + 90112 + 255) / 256;

    // CSR + tf32/fp16 pre-conversion (rank-producing histogram)
    k_conv_count<<<convBlocks + edgeBlocks, 256>>>(x, ei, Wres, Wl1, Wr1, Wl2, Wr2,
                                                   Wl3, Wr3, convBlocks);

    // fork: residual GEMM on side stream (depends only on xt/Wres from conv)
    cudaEventRecord(ev_fork, 0);
    cudaStreamWaitEvent(s_side, ev_fork, 0);
    gemm_tc<0><<<gemmBlocks, 256, GSMEM, s_side>>>(xt, wt + W_RES, nullptr, nullptr,
                                                   bres, hp, nullptr,
                                                   64, 0, 0, 0, nullptr, nullptr);
    cudaEventRecord(ev_join, s_side);

    // main: CSR chain + agg64 (independent of residual GEMM)
    k_scan1<<<NB, 1024>>>();
    k_scan3<<<NB, 1024>>>();
    k_fill<<<edgeBlocks, 256>>>(ei);
    agg_kernel<64><<<warpBlocks, 256>>>(x16, aggp);

    // join: layer-1 GEMM needs both hp (side) and agg (main)
    cudaStreamWaitEvent(0, ev_join, 0);

    // Layer 1: h = round(h + relu(LN(agg@Wl1 + xt@Wr1 + b1))), h16 shadow
    gemm_tc<1><<<gemmBlocks, 256, GSMEM>>>(aggp, wt + W_L1, xt, wt + W_R1, b1, hp,
                                           h16, 64, 1, 0, 0, ln_g, ln_b);

    // Layer 2: tmp = round(relu(agg128(h16)@Wl2 + h@Wr2 + b2)), tmp16 shadow
    agg_kernel<128><<<warpBlocks, 256>>>(h16, aggp);
    gemm_tc<0><<<gemmBlocks, 256, GSMEM>>>(aggp, wt + W_L2, hp, wt + W_R2, b2, tmpp,
                                           t16, 128, 1, 1, 1, nullptr, nullptr);

    // Layer 3+4a: zl/zr = relu(agg128(t16)@Wl3 + tmp@Wr3 + b3) . Wl4/Wr4
    agg_kernel<128><<<warpBlocks, 256>>>(t16, aggp);
    gemm_tc<2><<<gemmBlocks, 256, GSMEM>>>(aggp, wt + W_L3, tmpp, wt + W_R3, b3, nullptr,
                                           nullptr, 128, 1, 0, 0, Wl4, Wr4);

    // Layer 4b
    final_kernel<<<nodeBlocks, 256>>>(b4, out);
}

// round 16
// speedup vs baseline: 1.2120x; 1.2120x over previous
#include <cuda_runtime.h>
#include <cuda_fp16.h>
#include <cstdint>

#define NN 100000
#define EE 1600000
#define HH 128
#define NB ((NN + 1023) / 1024)   // 98 scan tiles

// ---------------- scratch (device globals; allocation-free) ----------------
__device__ float  g_h[(size_t)NN * HH];     // fp32 h (residual accumulator)
__device__ __half g_x16[(size_t)NN * 64];   // fp16 operand copies
__device__ __half g_h16[(size_t)NN * HH];
__device__ __half g_t16[(size_t)NN * HH];
__device__ __half g_agg16[(size_t)NN * HH];
__device__ __half g_wt16[90112];            // fp16 weights, TRANSPOSED [n][k]
__device__ float  g_deginv[NN];
__device__ int    g_deg[NN];
__device__ int    g_rank[EE];
__device__ int    g_rowptr[NN + 1];
__device__ int    g_bsum[NB];
__device__ int    g_csr[EE];
__device__ float  g_zl[NN];
__device__ float  g_zr[NN];

// weight offsets in g_wt16 (transposed [128 n][K k] each)
#define W_RES 0
#define W_L1  8192
#define W_R1  16384
#define W_L2  24576
#define W_R2  40960
#define W_L3  57344
#define W_R3  73728

// ---------------- helpers ----------------
__device__ __forceinline__ float tf32f(float x) {
    uint32_t r;
    asm("cvt.rna.tf32.f32 %0, %1;" : "=r"(r) : "f"(x));
    return __uint_as_float(r);
}
__device__ __forceinline__ uint32_t smem_u32(const void* p) {
    uint32_t a;
    asm("{ .reg .u64 t; cvta.to.shared.u64 t, %1; cvt.u32.u64 %0, t; }" : "=r"(a) : "l"(p));
    return a;
}
__device__ __forceinline__ void cp16(void* dst, const void* src, bool valid) {
    uint32_t d = smem_u32(dst);
    int sz = valid ? 16 : 0;
    asm volatile("cp.async.cg.shared.global [%0], [%1], 16, %2;"
                 :: "r"(d), "l"(src), "r"(sz) : "memory");
}

// ---------------- fused conv + degree histogram (rank-producing) ----------------
// edge_index is int32 (JAX x64 disabled => jnp.int64 silently becomes int32)
// Weights converted to fp16 and TRANSPOSED to [n][k] layout for the HMMA B operand.
__global__ void k_conv_count(const float* __restrict__ x, const int* __restrict__ ei,
                             const float* __restrict__ Wres, const float* __restrict__ Wl1,
                             const float* __restrict__ Wr1,  const float* __restrict__ Wl2,
                             const float* __restrict__ Wr2,  const float* __restrict__ Wl3,
                             const float* __restrict__ Wr3, int convBlocks) {
    if (blockIdx.x < (unsigned)convBlocks) {
        int i = blockIdx.x * 256 + threadIdx.x;
        const int NX = NN * 64;
        if (i < NX) { g_x16[i] = __float2half_rn(x[i]); return; }
        int j = i - NX;
        const float* W; int off, K;
        if      (j < 8192)  { W = Wres; off = W_RES; K = 64;  }
        else if (j < 16384) { W = Wl1;  off = W_L1;  K = 64;  j -= 8192;  }
        else if (j < 24576) { W = Wr1;  off = W_R1;  K = 64;  j -= 16384; }
        else if (j < 40960) { W = Wl2;  off = W_L2;  K = 128; j -= 24576; }
        else if (j < 57344) { W = Wr2;  off = W_R2;  K = 128; j -= 40960; }
        else if (j < 73728) { W = Wl3;  off = W_L3;  K = 128; j -= 57344; }
        else if (j < 90112) { W = Wr3;  off = W_R3;  K = 128; j -= 73728; }
        else return;
        int k = j >> 7, n = j & 127;               // input row-major [K][128]
        g_wt16[off + n * K + k] = __float2half_rn(W[j]);   // store [n][k]
    } else {
        int e = (blockIdx.x - convBlocks) * 256 + threadIdx.x;
        if (e >= EE) return;
        int d = ei[EE + e];
        d = min(max(d, 0), NN - 1);
        g_rank[e] = atomicAdd(&g_deg[d], 1);
    }
}

// pass 1: per-tile (1024) exclusive scan; tile totals; deginv; re-zero deg
__global__ __launch_bounds__(1024) void k_scan1() {
    __shared__ int wsum[32];
    int t = threadIdx.x;
    int lane = t & 31, w = t >> 5;
    int i = blockIdx.x * 1024 + t;
    int v = (i < NN) ? g_deg[i] : 0;
    int x = v;
    #pragma unroll
    for (int d = 1; d < 32; d <<= 1) {
        int y = __shfl_up_sync(0xffffffffu, x, d);
        if (lane >= d) x += y;
    }
    if (lane == 31) wsum[w] = x;
    __syncthreads();
    if (w == 0) {
        int s = wsum[lane];
        #pragma unroll
        for (int d = 1; d < 32; d <<= 1) {
            int y = __shfl_up_sync(0xffffffffu, s, d);
            if (lane >= d) s += y;
        }
        wsum[lane] = s;
    }
    __syncthreads();
    int incl = x + (w > 0 ? wsum[w - 1] : 0);
    if (i < NN) {
        g_rowptr[i] = incl - v;
        g_deginv[i] = 1.0f / fmaxf((float)v, 1.0f);
        g_deg[i] = 0;
    }
    if (t == 1023) g_bsum[blockIdx.x] = incl;
}

// pass 2 (merged): each block adds sum of preceding tile totals
__global__ __launch_bounds__(1024) void k_scan3() {
    __shared__ int ssum[32];
    int t = threadIdx.x;
    int lane = t & 31, w = t >> 5;
    int v = (t < blockIdx.x) ? g_bsum[t] : 0;
    #pragma unroll
    for (int d = 16; d; d >>= 1) v += __shfl_xor_sync(0xffffffffu, v, d);
    if (lane == 0) ssum[w] = v;
    __syncthreads();
    if (w == 0) {
        int s = ssum[lane];
        #pragma unroll
        for (int d = 16; d; d >>= 1) s += __shfl_xor_sync(0xffffffffu, s, d);
        if (lane == 0) ssum[0] = s;
    }
    __syncthreads();
    int off = ssum[0];
    int i = blockIdx.x * 1024 + t;
    if (i < NN) g_rowptr[i] += off;
    if (blockIdx.x == 0 && t == 0) g_rowptr[NN] = EE;
}

// atomic-free fill using precomputed ranks
__global__ void k_fill(const int* __restrict__ ei) {
    int e = blockIdx.x * blockDim.x + threadIdx.x;
    if (e >= EE) return;
    int s = ei[e];
    int d = ei[EE + e];
    s = min(max(s, 0), NN - 1);
    d = min(max(d, 0), NN - 1);
    g_csr[g_rowptr[d] + g_rank[e]] = s;
}

// ---------------- aggregation: warp per dst node, fp16 in/out, 8-way MLP ----------------
template <int F>
__global__ __launch_bounds__(256) void agg_kernel(const __half* __restrict__ in,
                                                  __half* __restrict__ out) {
    int warp = (blockIdx.x * blockDim.x + threadIdx.x) >> 5;
    int lane = threadIdx.x & 31;
    if (warp >= NN) return;
    int s = g_rowptr[warp], e = g_rowptr[warp + 1];
    float dinv = g_deginv[warp];
    if (F == 128) {
        float a0 = 0.f, a1 = 0.f, a2 = 0.f, a3 = 0.f;
        int j = s;
        for (; j + 8 <= e; j += 8) {
            int i0 = g_csr[j],     i1 = g_csr[j + 1], i2 = g_csr[j + 2], i3 = g_csr[j + 3];
            int i4 = g_csr[j + 4], i5 = g_csr[j + 5], i6 = g_csr[j + 6], i7 = g_csr[j + 7];
            uint2 v0 = __ldg((const uint2*)(in + (size_t)i0 * 128) + lane);
            uint2 v1 = __ldg((const uint2*)(in + (size_t)i1 * 128) + lane);
            uint2 v2 = __ldg((const uint2*)(in + (size_t)i2 * 128) + lane);
            uint2 v3 = __ldg((const uint2*)(in + (size_t)i3 * 128) + lane);
            uint2 v4 = __ldg((const uint2*)(in + (size_t)i4 * 128) + lane);
            uint2 v5 = __ldg((const uint2*)(in + (size_t)i5 * 128) + lane);
            uint2 v6 = __ldg((const uint2*)(in + (size_t)i6 * 128) + lane);
            uint2 v7 = __ldg((const uint2*)(in + (size_t)i7 * 128) + lane);
            float2 f;
            f = __half22float2(*(__half2*)&v0.x); a0 += f.x; a1 += f.y;
            f = __half22float2(*(__half2*)&v0.y); a2 += f.x; a3 += f.y;
            f = __half22float2(*(__half2*)&v1.x); a0 += f.x; a1 += f.y;
            f = __half22float2(*(__half2*)&v1.y); a2 += f.x; a3 += f.y;
            f = __half22float2(*(__half2*)&v2.x); a0 += f.x; a1 += f.y;
            f = __half22float2(*(__half2*)&v2.y); a2 += f.x; a3 += f.y;
            f = __half22float2(*(__half2*)&v3.x); a0 += f.x; a1 += f.y;
            f = __half22float2(*(__half2*)&v3.y); a2 += f.x; a3 += f.y;
            f = __half22float2(*(__half2*)&v4.x); a0 += f.x; a1 += f.y;
            f = __half22float2(*(__half2*)&v4.y); a2 += f.x; a3 += f.y;
            f = __half22float2(*(__half2*)&v5.x); a0 += f.x; a1 += f.y;
            f = __half22float2(*(__half2*)&v5.y); a2 += f.x; a3 += f.y;
            f = __half22float2(*(__half2*)&v6.x); a0 += f.x; a1 += f.y;
            f = __half22float2(*(__half2*)&v6.y); a2 += f.x; a3 += f.y;
            f = __half22float2(*(__half2*)&v7.x); a0 += f.x; a1 += f.y;
            f = __half22float2(*(__half2*)&v7.y); a2 += f.x; a3 += f.y;
        }
        #pragma unroll
        for (int k = 0; k < 7; k++) {
            if (j + k < e) {
                int src = g_csr[j + k];
                uint2 v = __ldg((const uint2*)(in + (size_t)src * 128) + lane);
                float2 f;
                f = __half22float2(*(__half2*)&v.x); a0 += f.x; a1 += f.y;
                f = __half22float2(*(__half2*)&v.y); a2 += f.x; a3 += f.y;
            }
        }
        uint2 o;
        *(__half2*)&o.x = __float22half2_rn(make_float2(a0 * dinv, a1 * dinv));
        *(__half2*)&o.y = __float22half2_rn(make_float2(a2 * dinv, a3 * dinv));
        ((uint2*)(out + (size_t)warp * 128))[lane] = o;
    } else {  // F == 64
        float a0 = 0.f, a1 = 0.f;
        int j = s;
        for (; j + 8 <= e; j += 8) {
            int i0 = g_csr[j],     i1 = g_csr[j + 1], i2 = g_csr[j + 2], i3 = g_csr[j + 3];
            int i4 = g_csr[j + 4], i5 = g_csr[j + 5], i6 = g_csr[j + 6], i7 = g_csr[j + 7];
            uint32_t v0 = __ldg((const uint32_t*)(in + (size_t)i0 * 64) + lane);
            uint32_t v1 = __ldg((const uint32_t*)(in + (size_t)i1 * 64) + lane);
            uint32_t v2 = __ldg((const uint32_t*)(in + (size_t)i2 * 64) + lane);
            uint32_t v3 = __ldg((const uint32_t*)(in + (size_t)i3 * 64) + lane);
            uint32_t v4 = __ldg((const uint32_t*)(in + (size_t)i4 * 64) + lane);
            uint32_t v5 = __ldg((const uint32_t*)(in + (size_t)i5 * 64) + lane);
            uint32_t v6 = __ldg((const uint32_t*)(in + (size_t)i6 * 64) + lane);
            uint32_t v7 = __ldg((const uint32_t*)(in + (size_t)i7 * 64) + lane);
            float2 f;
            f = __half22float2(*(__half2*)&v0); a0 += f.x; a1 += f.y;
            f = __half22float2(*(__half2*)&v1); a0 += f.x; a1 += f.y;
            f = __half22float2(*(__half2*)&v2); a0 += f.x; a1 += f.y;
            f = __half22float2(*(__half2*)&v3); a0 += f.x; a1 += f.y;
            f = __half22float2(*(__half2*)&v4); a0 += f.x; a1 += f.y;
            f = __half22float2(*(__half2*)&v5); a0 += f.x; a1 += f.y;
            f = __half22float2(*(__half2*)&v6); a0 += f.x; a1 += f.y;
            f = __half22float2(*(__half2*)&v7); a0 += f.x; a1 += f.y;
        }
        #pragma unroll
        for (int k = 0; k < 7; k++) {
            if (j + k < e) {
                int src = g_csr[j + k];
                uint32_t v = __ldg((const uint32_t*)(in + (size_t)src * 64) + lane);
                float2 f = __half22float2(*(__half2*)&v);
                a0 += f.x; a1 += f.y;
            }
        }
        __half2 o = __float22half2_rn(make_float2(a0 * dinv, a1 * dinv));
        ((__half2*)(out + (size_t)warp * 64))[lane] = o;
    }
}

// ---------------- fp16 mma.sync GEMM (m16n8k16), cp.async 3-stage pipeline ----------------
// A: [NN,K] fp16 row-major; W16: [128 n][K k] fp16 (pre-transposed); acc fp32.
// EPI: 0 = plain (bias, relu?, write C?/C16?); 1 = LN-residual into C + C16; 2 = projection
#define SA_H 40                                  // halves stride (32 k + 8 pad)
#define STAGEH (128 * SA_H + 128 * SA_H)         // 10240 halves = 20480 B per stage
#define GSMEM (3 * STAGEH * 2)                   // 61440 bytes

__device__ __forceinline__ void load_tiles(__half* stage,
                                           const __half* __restrict__ A,
                                           const __half* __restrict__ W16,
                                           int kk, int K, int row0, int tid) {
    __half* sA = stage;
    __half* sB = stage + 128 * SA_H;
    #pragma unroll
    for (int it = 0; it < 2; it++) {
        int idx = tid + it * 256;                // 0..511
        int r = idx >> 2, c8 = idx & 3;          // 16B (8-half) chunks
        int gr = row0 + r;
        cp16(&sA[r * SA_H + c8 * 8], &A[(size_t)gr * K + kk + c8 * 8], gr < NN);
    }
    #pragma unroll
    for (int it = 0; it < 2; it++) {
        int idx = tid + it * 256;
        int n = idx >> 2, c8 = idx & 3;
        cp16(&sB[n * SA_H + c8 * 8], &W16[(size_t)n * K + kk + c8 * 8], true);
    }
    asm volatile("cp.async.commit_group;" ::: "memory");
}

template <int EPI>
__global__ __launch_bounds__(256, 2) void gemm_tc(
    const __half* __restrict__ A1, const __half* __restrict__ W1,
    const __half* __restrict__ A2, const __half* __restrict__ W2,
    const float* __restrict__ bias, float* __restrict__ C,
    __half* __restrict__ C16,
    int K, int dual, int relu,
    const float* __restrict__ q1, const float* __restrict__ q2)
{
    extern __shared__ __half smem[];

    int tid = threadIdx.x;
    int wid = tid >> 5, lane = tid & 31;
    int g = lane >> 2, t = lane & 3;
    int row0 = blockIdx.x * 128;
    int mrow = (wid & 3) * 32;
    int ncol = (wid >> 2) * 64;
    int half_id = wid >> 2;

    float acc[2][8][4];
    #pragma unroll
    for (int mi = 0; mi < 2; mi++)
        #pragma unroll
        for (int nj = 0; nj < 8; nj++)
            #pragma unroll
            for (int q = 0; q < 4; q++) acc[mi][nj][q] = 0.f;

    int KT = dual ? 2 * K : K;
    int niter = KT >> 5;

    load_tiles(smem, A1, W1, 0, K, row0, tid);
    if (niter > 1) {
        const __half* A = A1;
        const __half* W = W1;
        int kk = 32;
        if (kk >= K) { A = A2; W = W2; kk -= K; }
        load_tiles(smem + STAGEH, A, W, kk, K, row0, tid);
    }

    int stage = 0;
    for (int itn = 0; itn < niter; itn++) {
        if (itn + 1 < niter)
            asm volatile("cp.async.wait_group 1;" ::: "memory");
        else
            asm volatile("cp.async.wait_group 0;" ::: "memory");
        __syncthreads();

        int pf = itn + 2;
        if (pf < niter) {
            int k0 = pf * 32;
            const __half* A = A1;
            const __half* W = W1;
            int kk = k0;
            if (k0 >= K) { A = A2; W = W2; kk = k0 - K; }
            int pstage = stage + 2; if (pstage >= 3) pstage -= 3;
            load_tiles(smem + pstage * STAGEH, A, W, kk, K, row0, tid);
        }

        const uint32_t* sA4 = (const uint32_t*)(smem + stage * STAGEH);
        const uint32_t* sB4 = sA4 + 128 * (SA_H / 2);

        #pragma unroll
        for (int ks = 0; ks < 2; ks++) {         // two k16 steps per BK=32
            int kb = ks * 8;                     // in 4B units
            uint32_t af[2][4];
            #pragma unroll
            for (int mi = 0; mi < 2; mi++) {
                int br = mrow + mi * 16;
                af[mi][0] = sA4[(br + g) * 20 + kb + t];
                af[mi][1] = sA4[(br + g + 8) * 20 + kb + t];
                af[mi][2] = sA4[(br + g) * 20 + kb + t + 4];
                af[mi][3] = sA4[(br + g + 8) * 20 + kb + t + 4];
            }
            uint32_t bf[8][2];
            #pragma unroll
            for (int nj = 0; nj < 8; nj++) {
                int n = ncol + nj * 8 + g;
                bf[nj][0] = sB4[n * 20 + kb + t];
                bf[nj][1] = sB4[n * 20 + kb + t + 4];
            }
            #pragma unroll
            for (int mi = 0; mi < 2; mi++)
                #pragma unroll
                for (int nj = 0; nj < 8; nj++) {
                    asm volatile(
                        "mma.sync.aligned.m16n8k16.row.col.f32.f16.f16.f32 "
                        "{%0,%1,%2,%3}, {%4,%5,%6,%7}, {%8,%9}, {%0,%1,%2,%3};"
                        : "+f"(acc[mi][nj][0]), "+f"(acc[mi][nj][1]),
                          "+f"(acc[mi][nj][2]), "+f"(acc[mi][nj][3])
                        : "r"(af[mi][0]), "r"(af[mi][1]), "r"(af[mi][2]), "r"(af[mi][3]),
                          "r"(bf[nj][0]), "r"(bf[nj][1]));
                }
        }
        if (++stage == 3) stage = 0;
    }

    float bv0[8], bv1[8];
    #pragma unroll
    for (int nj = 0; nj < 8; nj++) {
        int col = ncol + nj * 8 + 2 * t;
        bv0[nj] = bias[col]; bv1[nj] = bias[col + 1];
    }

    if (EPI == 0) {
        #pragma unroll
        for (int mi = 0; mi < 2; mi++) {
            int r_lo = row0 + mrow + mi * 16 + g;
            int r_hi = r_lo + 8;
            #pragma unroll
            for (int nj = 0; nj < 8; nj++) {
                int col = ncol + nj * 8 + 2 * t;
                float2 v0, v1;
                v0.x = acc[mi][nj][0] + bv0[nj]; v0.y = acc[mi][nj][1] + bv1[nj];
                v1.x = acc[mi][nj][2] + bv0[nj]; v1.y = acc[mi][nj][3] + bv1[nj];
                if (relu) {
                    v0.x = fmaxf(v0.x, 0.f); v0.y = fmaxf(v0.y, 0.f);
                    v1.x = fmaxf(v1.x, 0.f); v1.y = fmaxf(v1.y, 0.f);
                }
                if (r_lo < NN) {
                    if (C)   *(float2*)&C[(size_t)r_lo * 128 + col] = v0;
                    if (C16) *(__half2*)&C16[(size_t)r_lo * 128 + col] = __float22half2_rn(v0);
                }
                if (r_hi < NN) {
                    if (C)   *(float2*)&C[(size_t)r_hi * 128 + col] = v1;
                    if (C16) *(__half2*)&C16[(size_t)r_hi * 128 + col] = __float22half2_rn(v1);
                }
            }
        }
    } else if (EPI == 1) {
        float S[4] = {0.f, 0.f, 0.f, 0.f}, Q[4] = {0.f, 0.f, 0.f, 0.f};
        #pragma unroll
        for (int mi = 0; mi < 2; mi++)
            #pragma unroll
            for (int nj = 0; nj < 8; nj++) {
                float a0 = acc[mi][nj][0] + bv0[nj], a1 = acc[mi][nj][1] + bv1[nj];
                float a2 = acc[mi][nj][2] + bv0[nj], a3 = acc[mi][nj][3] + bv1[nj];
                S[mi * 2]     += a0 + a1; Q[mi * 2]     += a0 * a0 + a1 * a1;
                S[mi * 2 + 1] += a2 + a3; Q[mi * 2 + 1] += a2 * a2 + a3 * a3;
            }
        #pragma unroll
        for (int ri = 0; ri < 4; ri++) {
            S[ri] += __shfl_xor_sync(0xffffffffu, S[ri], 1);
            S[ri] += __shfl_xor_sync(0xffffffffu, S[ri], 2);
            Q[ri] += __shfl_xor_sync(0xffffffffu, Q[ri], 1);
            Q[ri] += __shfl_xor_sync(0xffffffffu, Q[ri], 2);
        }
        float2* red = (float2*)smem;
        __syncthreads();
        if (t == 0) {
            #pragma unroll
            for (int ri = 0; ri < 4; ri++) {
                int row = mrow + (ri >> 1) * 16 + g + (ri & 1) * 8;
                red[row * 2 + half_id] = make_float2(S[ri], Q[ri]);
            }
        }
        __syncthreads();
        float mu[4], rs[4];
        #pragma unroll
        for (int ri = 0; ri < 4; ri++) {
            int row = mrow + (ri >> 1) * 16 + g + (ri & 1) * 8;
            float2 p0 = red[row * 2], p1 = red[row * 2 + 1];
            float Sf = p0.x + p1.x, Qf = p0.y + p1.y;
            mu[ri] = Sf * (1.0f / 128.0f);
            float var = Qf * (1.0f / 128.0f) - mu[ri] * mu[ri];
            rs[ri] = rsqrtf(var + 1e-5f);
        }
        #pragma unroll
        for (int mi = 0; mi < 2; mi++) {
            int r_lo = row0 + mrow + mi * 16 + g;
            int r_hi = r_lo + 8;
            #pragma unroll
            for (int nj = 0; nj < 8; nj++) {
                int col = ncol + nj * 8 + 2 * t;
                float g0 = q1[col], g1 = q1[col + 1];
                float e0 = q2[col], e1 = q2[col + 1];
                if (r_lo < NN) {
                    float a0 = acc[mi][nj][0] + bv0[nj], a1 = acc[mi][nj][1] + bv1[nj];
                    float o0 = fmaxf((a0 - mu[mi * 2]) * rs[mi * 2] * g0 + e0, 0.f);
                    float o1 = fmaxf((a1 - mu[mi * 2]) * rs[mi * 2] * g1 + e1, 0.f);
                    float2 hv = *(float2*)&C[(size_t)r_lo * 128 + col];
                    hv.x = tf32f(hv.x + o0); hv.y = tf32f(hv.y + o1);
                    *(float2*)&C[(size_t)r_lo * 128 + col] = hv;
                    *(__half2*)&C16[(size_t)r_lo * 128 + col] = __float22half2_rn(hv);
                }
                if (r_hi < NN) {
                    float a2 = acc[mi][nj][2] + bv0[nj], a3 = acc[mi][nj][3] + bv1[nj];
                    float o2 = fmaxf((a2 - mu[mi * 2 + 1]) * rs[mi * 2 + 1] * g0 + e0, 0.f);
                    float o3 = fmaxf((a3 - mu[mi * 2 + 1]) * rs[mi * 2 + 1] * g1 + e1, 0.f);
                    float2 hv = *(float2*)&C[(size_t)r_hi * 128 + col];
                    hv.x = tf32f(hv.x + o2); hv.y = tf32f(hv.y + o3);
                    *(float2*)&C[(size_t)r_hi * 128 + col] = hv;
                    *(__half2*)&C16[(size_t)r_hi * 128 + col] = __float22half2_rn(hv);
                }
            }
        }
    } else {
        float sl[4] = {0.f, 0.f, 0.f, 0.f}, sr[4] = {0.f, 0.f, 0.f, 0.f};
        #pragma unroll
        for (int nj = 0; nj < 8; nj++) {
            int col = ncol + nj * 8 + 2 * t;
            float wl0 = __ldg(&q1[col]), wl1 = __ldg(&q1[col + 1]);
            float wr0 = __ldg(&q2[col]), wr1 = __ldg(&q2[col + 1]);
            #pragma unroll
            for (int mi = 0; mi < 2; mi++) {
                float a0 = fmaxf(acc[mi][nj][0] + bv0[nj], 0.f);
                float a1 = fmaxf(acc[mi][nj][1] + bv1[nj], 0.f);
                float a2 = fmaxf(acc[mi][nj][2] + bv0[nj], 0.f);
                float a3 = fmaxf(acc[mi][nj][3] + bv1[nj], 0.f);
                sl[mi * 2]     += a0 * wl0 + a1 * wl1;
                sr[mi * 2]     += a0 * wr0 + a1 * wr1;
                sl[mi * 2 + 1] += a2 * wl0 + a3 * wl1;
                sr[mi * 2 + 1] += a2 * wr0 + a3 * wr1;
            }
        }
        #pragma unroll
        for (int ri = 0; ri < 4; ri++) {
            sl[ri] += __shfl_xor_sync(0xffffffffu, sl[ri], 1);
            sl[ri] += __shfl_xor_sync(0xffffffffu, sl[ri], 2);
            sr[ri] += __shfl_xor_sync(0xffffffffu, sr[ri], 1);
            sr[ri] += __shfl_xor_sync(0xffffffffu, sr[ri], 2);
        }
        float2* red = (float2*)smem;
        __syncthreads();
        if (t == 0) {
            #pragma unroll
            for (int ri = 0; ri < 4; ri++) {
                int row = mrow + (ri >> 1) * 16 + g + (ri & 1) * 8;
                red[row * 2 + half_id] = make_float2(sl[ri], sr[ri]);
            }
        }
        __syncthreads();
        if (t == 0 && half_id == 0) {
            #pragma unroll
            for (int ri = 0; ri < 4; ri++) {
                int row = mrow + (ri >> 1) * 16 + g + (ri & 1) * 8;
                int gr = row0 + row;
                if (gr < NN) {
                    float2 p0 = red[row * 2], p1 = red[row * 2 + 1];
                    g_zl[gr] = p0.x + p1.x;
                    g_zr[gr] = p0.y + p1.y;
                }
            }
        }
    }
}

// ---------------- final: out = zr + b4 + deginv * sum(zl[neighbors]) ----------------
__global__ void final_kernel(const float* __restrict__ b4, float* __restrict__ out) {
    int i = blockIdx.x * blockDim.x + threadIdx.x;
    if (i >= NN) return;
    int s = g_rowptr[i], e = g_rowptr[i + 1];
    float sum = 0.f;
    int j = s;
    for (; j + 4 <= e; j += 4) {
        float z0 = __ldg(&g_zl[g_csr[j]]);
        float z1 = __ldg(&g_zl[g_csr[j + 1]]);
        float z2 = __ldg(&g_zl[g_csr[j + 2]]);
        float z3 = __ldg(&g_zl[g_csr[j + 3]]);
        sum += (z0 + z1) + (z2 + z3);
    }
    for (; j < e; j++) sum += __ldg(&g_zl[g_csr[j]]);
    out[i] = g_zr[i] + b4[0] + g_deginv[i] * sum;
}

// ---------------- host ----------------
template <typename T>
static T* sym(const void* s) {
    void* p = nullptr;
    cudaGetSymbolAddress(&p, s);
    return (T*)p;
}

extern "C" void kernel_launch(void* const* d_in, const int* in_sizes, int n_in,
                              void* d_out, int out_size) {
    const float* x    = (const float*)d_in[0];
    const int*   ei   = (const int*)d_in[1];     // int32 (JAX x64 disabled)
    const float* Wl1  = (const float*)d_in[2];
    const float* Wr1  = (const float*)d_in[3];
    const float* b1   = (const float*)d_in[4];
    const float* ln_g = (const float*)d_in[5];
    const float* ln_b = (const float*)d_in[6];
    const float* Wres = (const float*)d_in[7];
    const float* bres = (const float*)d_in[8];
    const float* Wl2  = (const float*)d_in[9];
    const float* Wr2  = (const float*)d_in[10];
    const float* b2   = (const float*)d_in[11];
    const float* Wl3  = (const float*)d_in[12];
    const float* Wr3  = (const float*)d_in[13];
    const float* b3   = (const float*)d_in[14];
    const float* Wl4  = (const float*)d_in[15];
    const float* Wr4  = (const float*)d_in[16];
    const float* b4   = (const float*)d_in[17];
    float* out = (float*)d_out;

    float*  hp    = sym<float>(g_h);
    __half* x16   = sym<__half>(g_x16);
    __half* h16   = sym<__half>(g_h16);
    __half* t16   = sym<__half>(g_t16);
    __half* agg16 = sym<__half>(g_agg16);
    __half* wt16  = sym<__half>(g_wt16);

    static int inited = 0;
    if (!inited) {
        inited = 1;
        cudaFuncSetAttribute(gemm_tc<0>, cudaFuncAttributeMaxDynamicSharedMemorySize, GSMEM);
        cudaFuncSetAttribute(gemm_tc<1>, cudaFuncAttributeMaxDynamicSharedMemorySize, GSMEM);
        cudaFuncSetAttribute(gemm_tc<2>, cudaFuncAttributeMaxDynamicSharedMemorySize, GSMEM);
    }

    const int warpBlocks = (NN + 7) / 8;          // 12500
    const int gemmBlocks = (NN + 127) / 128;      // 782
    const int edgeBlocks = (EE + 255) / 256;
    const int nodeBlocks = (NN + 255) / 256;
    const int convBlocks = (NN * 64 + 90112 + 255) / 256;

    // CSR + fp16 pre-conversion (weights transposed), rank-producing histogram
    k_conv_count<<<convBlocks + edgeBlocks, 256>>>(x, ei, Wres, Wl1, Wr1, Wl2, Wr2,
                                                   Wl3, Wr3, convBlocks);
    k_scan1<<<NB, 1024>>>();
    // residual: h = x16 @ Wres^T + bres (fp32 out, no fp16 shadow needed)
    gemm_tc<0><<<gemmBlocks, 256, GSMEM>>>(x16, wt16 + W_RES, nullptr, nullptr, bres,
                                           hp, nullptr, 64, 0, 0, nullptr, nullptr);
    k_scan3<<<NB, 1024>>>();
    k_fill<<<edgeBlocks, 256>>>(ei);

    // Layer 1: agg64(x16) -> agg16; h = h + relu(LN(agg@Wl1 + x16@Wr1 + b1)); h16 shadow
    agg_kernel<64><<<warpBlocks, 256>>>(x16, agg16);
    gemm_tc<1><<<gemmBlocks, 256, GSMEM>>>(agg16, wt16 + W_L1, x16, wt16 + W_R1, b1,
                                           hp, h16, 64, 1, 0, ln_g, ln_b);

    // Layer 2: t16 = relu(agg128(h16)@Wl2 + h16@Wr2 + b2)  (fp16 only — no fp32 tmp)
    agg_kernel<128><<<warpBlocks, 256>>>(h16, agg16);
    gemm_tc<0><<<gemmBlocks, 256, GSMEM>>>(agg16, wt16 + W_L2, h16, wt16 + W_R2, b2,
                                           nullptr, t16, 128, 1, 1, nullptr, nullptr);

    // Layer 3+4a: zl/zr = relu(agg128(t16)@Wl3 + t16@Wr3 + b3) . Wl4/Wr4
    agg_kernel<128><<<warpBlocks, 256>>>(t16, agg16);
    gemm_tc<2><<<gemmBlocks, 256, GSMEM>>>(agg16, wt16 + W_L3, t16, wt16 + W_R3, b3,
                                           nullptr, nullptr, 128, 1, 0, Wl4, Wr4);

    // Layer 4b
    final_kernel<<<nodeBlocks, 256>>>(b4, out);
}

// round 17
// speedup vs baseline: 1.3038x; 1.0757x over previous
#include <cuda_runtime.h>
#include <cuda_fp16.h>
#include <cstdint>

#define NN 100000
#define EE 1600000
#define HH 128
#define NB ((NN + 1023) / 1024)   // 98 scan tiles

// ---------------- scratch (device globals; allocation-free) ----------------
__device__ __half g_x16[(size_t)NN * 64];   // fp16 operand copies
__device__ __half g_h16[(size_t)NN * HH];
__device__ __half g_t16[(size_t)NN * HH];   // doubles as residual buffer pre-layer1
__device__ __half g_agg16[(size_t)NN * HH];
__device__ __half g_wt16[90112];            // fp16 weights, TRANSPOSED [n][k]
__device__ float  g_deginv[NN];
__device__ int    g_deg[NN];
__device__ int    g_rank[EE];
__device__ int    g_rowptr[NN + 1];
__device__ int    g_bsum[NB];
__device__ int    g_csr[EE];
__device__ float  g_zl[NN];
__device__ float  g_zr[NN];

// weight offsets in g_wt16 (transposed [128 n][K k] each)
#define W_RES 0
#define W_L1  8192
#define W_R1  16384
#define W_L2  24576
#define W_R2  40960
#define W_L3  57344
#define W_R3  73728

// ---------------- helpers ----------------
__device__ __forceinline__ uint32_t smem_u32(const void* p) {
    uint32_t a;
    asm("{ .reg .u64 t; cvta.to.shared.u64 t, %1; cvt.u32.u64 %0, t; }" : "=r"(a) : "l"(p));
    return a;
}
__device__ __forceinline__ void cp16(void* dst, const void* src, bool valid) {
    uint32_t d = smem_u32(dst);
    int sz = valid ? 16 : 0;
    asm volatile("cp.async.cg.shared.global [%0], [%1], 16, %2;"
                 :: "r"(d), "l"(src), "r"(sz) : "memory");
}

// ---------------- fused conv + degree histogram (rank-producing) ----------------
// edge_index is int32 (JAX x64 disabled => jnp.int64 silently becomes int32)
__global__ void k_conv_count(const float* __restrict__ x, const int* __restrict__ ei,
                             const float* __restrict__ Wres, const float* __restrict__ Wl1,
                             const float* __restrict__ Wr1,  const float* __restrict__ Wl2,
                             const float* __restrict__ Wr2,  const float* __restrict__ Wl3,
                             const float* __restrict__ Wr3, int convBlocks) {
    if (blockIdx.x < (unsigned)convBlocks) {
        int i = blockIdx.x * 256 + threadIdx.x;
        const int NX = NN * 64;
        if (i < NX) { g_x16[i] = __float2half_rn(x[i]); return; }
        int j = i - NX;
        const float* W; int off, K;
        if      (j < 8192)  { W = Wres; off = W_RES; K = 64;  }
        else if (j < 16384) { W = Wl1;  off = W_L1;  K = 64;  j -= 8192;  }
        else if (j < 24576) { W = Wr1;  off = W_R1;  K = 64;  j -= 16384; }
        else if (j < 40960) { W = Wl2;  off = W_L2;  K = 128; j -= 24576; }
        else if (j < 57344) { W = Wr2;  off = W_R2;  K = 128; j -= 40960; }
        else if (j < 73728) { W = Wl3;  off = W_L3;  K = 128; j -= 57344; }
        else if (j < 90112) { W = Wr3;  off = W_R3;  K = 128; j -= 73728; }
        else return;
        int k = j >> 7, n = j & 127;
        g_wt16[off + n * K + k] = __float2half_rn(W[j]);
    } else {
        int e = (blockIdx.x - convBlocks) * 256 + threadIdx.x;
        if (e >= EE) return;
        int d = ei[EE + e];
        d = min(max(d, 0), NN - 1);
        g_rank[e] = atomicAdd(&g_deg[d], 1);
    }
}

// pass 1: per-tile (1024) exclusive scan; tile totals; deginv; re-zero deg
__global__ __launch_bounds__(1024) void k_scan1() {
    __shared__ int wsum[32];
    int t = threadIdx.x;
    int lane = t & 31, w = t >> 5;
    int i = blockIdx.x * 1024 + t;
    int v = (i < NN) ? g_deg[i] : 0;
    int x = v;
    #pragma unroll
    for (int d = 1; d < 32; d <<= 1) {
        int y = __shfl_up_sync(0xffffffffu, x, d);
        if (lane >= d) x += y;
    }
    if (lane == 31) wsum[w] = x;
    __syncthreads();
    if (w == 0) {
        int s = wsum[lane];
        #pragma unroll
        for (int d = 1; d < 32; d <<= 1) {
            int y = __shfl_up_sync(0xffffffffu, s, d);
            if (lane >= d) s += y;
        }
        wsum[lane] = s;
    }
    __syncthreads();
    int incl = x + (w > 0 ? wsum[w - 1] : 0);
    if (i < NN) {
        g_rowptr[i] = incl - v;
        g_deginv[i] = 1.0f / fmaxf((float)v, 1.0f);
        g_deg[i] = 0;
    }
    if (t == 1023) g_bsum[blockIdx.x] = incl;
}

// pass 2 (merged): each block adds sum of preceding tile totals
__global__ __launch_bounds__(1024) void k_scan3() {
    __shared__ int ssum[32];
    int t = threadIdx.x;
    int lane = t & 31, w = t >> 5;
    int v = (t < blockIdx.x) ? g_bsum[t] : 0;
    #pragma unroll
    for (int d = 16; d; d >>= 1) v += __shfl_xor_sync(0xffffffffu, v, d);
    if (lane == 0) ssum[w] = v;
    __syncthreads();
    if (w == 0) {
        int s = ssum[lane];
        #pragma unroll
        for (int d = 16; d; d >>= 1) s += __shfl_xor_sync(0xffffffffu, s, d);
        if (lane == 0) ssum[0] = s;
    }
    __syncthreads();
    int off = ssum[0];
    int i = blockIdx.x * 1024 + t;
    if (i < NN) g_rowptr[i] += off;
    if (blockIdx.x == 0 && t == 0) g_rowptr[NN] = EE;
}

// atomic-free fill using precomputed ranks
__global__ void k_fill(const int* __restrict__ ei) {
    int e = blockIdx.x * blockDim.x + threadIdx.x;
    if (e >= EE) return;
    int s = ei[e];
    int d = ei[EE + e];
    s = min(max(s, 0), NN - 1);
    d = min(max(d, 0), NN - 1);
    g_csr[g_rowptr[d] + g_rank[e]] = s;
}

// ---------------- aggregation: warp per dst node, fp16 in/out, 8-way MLP ----------------
template <int F>
__global__ __launch_bounds__(256) void agg_kernel(const __half* __restrict__ in,
                                                  __half* __restrict__ out) {
    int warp = (blockIdx.x * blockDim.x + threadIdx.x) >> 5;
    int lane = threadIdx.x & 31;
    if (warp >= NN) return;
    int s = g_rowptr[warp], e = g_rowptr[warp + 1];
    float dinv = g_deginv[warp];
    if (F == 128) {
        float a0 = 0.f, a1 = 0.f, a2 = 0.f, a3 = 0.f;
        int j = s;
        for (; j + 8 <= e; j += 8) {
            int i0 = g_csr[j],     i1 = g_csr[j + 1], i2 = g_csr[j + 2], i3 = g_csr[j + 3];
            int i4 = g_csr[j + 4], i5 = g_csr[j + 5], i6 = g_csr[j + 6], i7 = g_csr[j + 7];
            uint2 v0 = __ldg((const uint2*)(in + (size_t)i0 * 128) + lane);
            uint2 v1 = __ldg((const uint2*)(in + (size_t)i1 * 128) + lane);
            uint2 v2 = __ldg((const uint2*)(in + (size_t)i2 * 128) + lane);
            uint2 v3 = __ldg((const uint2*)(in + (size_t)i3 * 128) + lane);
            uint2 v4 = __ldg((const uint2*)(in + (size_t)i4 * 128) + lane);
            uint2 v5 = __ldg((const uint2*)(in + (size_t)i5 * 128) + lane);
            uint2 v6 = __ldg((const uint2*)(in + (size_t)i6 * 128) + lane);
            uint2 v7 = __ldg((const uint2*)(in + (size_t)i7 * 128) + lane);
            float2 f;
            f = __half22float2(*(__half2*)&v0.x); a0 += f.x; a1 += f.y;
            f = __half22float2(*(__half2*)&v0.y); a2 += f.x; a3 += f.y;
            f = __half22float2(*(__half2*)&v1.x); a0 += f.x; a1 += f.y;
            f = __half22float2(*(__half2*)&v1.y); a2 += f.x; a3 += f.y;
            f = __half22float2(*(__half2*)&v2.x); a0 += f.x; a1 += f.y;
            f = __half22float2(*(__half2*)&v2.y); a2 += f.x; a3 += f.y;
            f = __half22float2(*(__half2*)&v3.x); a0 += f.x; a1 += f.y;
            f = __half22float2(*(__half2*)&v3.y); a2 += f.x; a3 += f.y;
            f = __half22float2(*(__half2*)&v4.x); a0 += f.x; a1 += f.y;
            f = __half22float2(*(__half2*)&v4.y); a2 += f.x; a3 += f.y;
            f = __half22float2(*(__half2*)&v5.x); a0 += f.x; a1 += f.y;
            f = __half22float2(*(__half2*)&v5.y); a2 += f.x; a3 += f.y;
            f = __half22float2(*(__half2*)&v6.x); a0 += f.x; a1 += f.y;
            f = __half22float2(*(__half2*)&v6.y); a2 += f.x; a3 += f.y;
            f = __half22float2(*(__half2*)&v7.x); a0 += f.x; a1 += f.y;
            f = __half22float2(*(__half2*)&v7.y); a2 += f.x; a3 += f.y;
        }
        #pragma unroll
        for (int k = 0; k < 7; k++) {
            if (j + k < e) {
                int src = g_csr[j + k];
                uint2 v = __ldg((const uint2*)(in + (size_t)src * 128) + lane);
                float2 f;
                f = __half22float2(*(__half2*)&v.x); a0 += f.x; a1 += f.y;
                f = __half22float2(*(__half2*)&v.y); a2 += f.x; a3 += f.y;
            }
        }
        uint2 o;
        *(__half2*)&o.x = __float22half2_rn(make_float2(a0 * dinv, a1 * dinv));
        *(__half2*)&o.y = __float22half2_rn(make_float2(a2 * dinv, a3 * dinv));
        ((uint2*)(out + (size_t)warp * 128))[lane] = o;
    } else {  // F == 64
        float a0 = 0.f, a1 = 0.f;
        int j = s;
        for (; j + 8 <= e; j += 8) {
            int i0 = g_csr[j],     i1 = g_csr[j + 1], i2 = g_csr[j + 2], i3 = g_csr[j + 3];
            int i4 = g_csr[j + 4], i5 = g_csr[j + 5], i6 = g_csr[j + 6], i7 = g_csr[j + 7];
            uint32_t v0 = __ldg((const uint32_t*)(in + (size_t)i0 * 64) + lane);
            uint32_t v1 = __ldg((const uint32_t*)(in + (size_t)i1 * 64) + lane);
            uint32_t v2 = __ldg((const uint32_t*)(in + (size_t)i2 * 64) + lane);
            uint32_t v3 = __ldg((const uint32_t*)(in + (size_t)i3 * 64) + lane);
            uint32_t v4 = __ldg((const uint32_t*)(in + (size_t)i4 * 64) + lane);
            uint32_t v5 = __ldg((const uint32_t*)(in + (size_t)i5 * 64) + lane);
            uint32_t v6 = __ldg((const uint32_t*)(in + (size_t)i6 * 64) + lane);
            uint32_t v7 = __ldg((const uint32_t*)(in + (size_t)i7 * 64) + lane);
            float2 f;
            f = __half22float2(*(__half2*)&v0); a0 += f.x; a1 += f.y;
            f = __half22float2(*(__half2*)&v1); a0 += f.x; a1 += f.y;
            f = __half22float2(*(__half2*)&v2); a0 += f.x; a1 += f.y;
            f = __half22float2(*(__half2*)&v3); a0 += f.x; a1 += f.y;
            f = __half22float2(*(__half2*)&v4); a0 += f.x; a1 += f.y;
            f = __half22float2(*(__half2*)&v5); a0 += f.x; a1 += f.y;
            f = __half22float2(*(__half2*)&v6); a0 += f.x; a1 += f.y;
            f = __half22float2(*(__half2*)&v7); a0 += f.x; a1 += f.y;
        }
        #pragma unroll
        for (int k = 0; k < 7; k++) {
            if (j + k < e) {
                int src = g_csr[j + k];
                uint32_t v = __ldg((const uint32_t*)(in + (size_t)src * 64) + lane);
                float2 f = __half22float2(*(__half2*)&v);
                a0 += f.x; a1 += f.y;
            }
        }
        __half2 o = __float22half2_rn(make_float2(a0 * dinv, a1 * dinv));
        ((__half2*)(out + (size_t)warp * 64))[lane] = o;
    }
}

// ---------------- fp16 mma.sync GEMM (m16n8k16), cp.async 3-stage pipeline ----------------
// A: [NN,K] fp16 row-major; W16: [128 n][K k] fp16 (pre-transposed); acc fp32.
// EPI: 0 = plain (bias, relu?, write C16); 1 = LN-residual: C16 = h16 = R16 + relu(LN(...));
//      2 = projection to zl/zr
#define SA_H 40
#define STAGEH (128 * SA_H + 128 * SA_H)         // 10240 halves = 20480 B per stage
#define GSMEM (3 * STAGEH * 2)                   // 61440 bytes

__device__ __forceinline__ void load_tiles(__half* stage,
                                           const __half* __restrict__ A,
                                           const __half* __restrict__ W16,
                                           int kk, int K, int row0, int tid) {
    __half* sA = stage;
    __half* sB = stage + 128 * SA_H;
    #pragma unroll
    for (int it = 0; it < 2; it++) {
        int idx = tid + it * 256;
        int r = idx >> 2, c8 = idx & 3;
        int gr = row0 + r;
        cp16(&sA[r * SA_H + c8 * 8], &A[(size_t)gr * K + kk + c8 * 8], gr < NN);
    }
    #pragma unroll
    for (int it = 0; it < 2; it++) {
        int idx = tid + it * 256;
        int n = idx >> 2, c8 = idx & 3;
        cp16(&sB[n * SA_H + c8 * 8], &W16[(size_t)n * K + kk + c8 * 8], true);
    }
    asm volatile("cp.async.commit_group;" ::: "memory");
}

template <int EPI>
__global__ __launch_bounds__(256, 2) void gemm_tc(
    const __half* __restrict__ A1, const __half* __restrict__ W1,
    const __half* __restrict__ A2, const __half* __restrict__ W2,
    const float* __restrict__ bias, const __half* __restrict__ R16,
    __half* __restrict__ C16,
    int K, int dual, int relu,
    const float* __restrict__ q1, const float* __restrict__ q2)
{
    extern __shared__ __half smem[];

    int tid = threadIdx.x;
    int wid = tid >> 5, lane = tid & 31;
    int g = lane >> 2, t = lane & 3;
    int row0 = blockIdx.x * 128;
    int mrow = (wid & 3) * 32;
    int ncol = (wid >> 2) * 64;
    int half_id = wid >> 2;

    float acc[2][8][4];
    #pragma unroll
    for (int mi = 0; mi < 2; mi++)
        #pragma unroll
        for (int nj = 0; nj < 8; nj++)
            #pragma unroll
            for (int q = 0; q < 4; q++) acc[mi][nj][q] = 0.f;

    int KT = dual ? 2 * K : K;
    int niter = KT >> 5;

    load_tiles(smem, A1, W1, 0, K, row0, tid);
    if (niter > 1) {
        const __half* A = A1;
        const __half* W = W1;
        int kk = 32;
        if (kk >= K) { A = A2; W = W2; kk -= K; }
        load_tiles(smem + STAGEH, A, W, kk, K, row0, tid);
    }

    int stage = 0;
    for (int itn = 0; itn < niter; itn++) {
        if (itn + 1 < niter)
            asm volatile("cp.async.wait_group 1;" ::: "memory");
        else
            asm volatile("cp.async.wait_group 0;" ::: "memory");
        __syncthreads();

        int pf = itn + 2;
        if (pf < niter) {
            int k0 = pf * 32;
            const __half* A = A1;
            const __half* W = W1;
            int kk = k0;
            if (k0 >= K) { A = A2; W = W2; kk = k0 - K; }
            int pstage = stage + 2; if (pstage >= 3) pstage -= 3;
            load_tiles(smem + pstage * STAGEH, A, W, kk, K, row0, tid);
        }

        const uint32_t* sA4 = (const uint32_t*)(smem + stage * STAGEH);
        const uint32_t* sB4 = sA4 + 128 * (SA_H / 2);

        #pragma unroll
        for (int ks = 0; ks < 2; ks++) {
            int kb = ks * 8;
            uint32_t af[2][4];
            #pragma unroll
            for (int mi = 0; mi < 2; mi++) {
                int br = mrow + mi * 16;
                af[mi][0] = sA4[(br + g) * 20 + kb + t];
                af[mi][1] = sA4[(br + g + 8) * 20 + kb + t];
                af[mi][2] = sA4[(br + g) * 20 + kb + t + 4];
                af[mi][3] = sA4[(br + g + 8) * 20 + kb + t + 4];
            }
            uint32_t bf[8][2];
            #pragma unroll
            for (int nj = 0; nj < 8; nj++) {
                int n = ncol + nj * 8 + g;
                bf[nj][0] = sB4[n * 20 + kb + t];
                bf[nj][1] = sB4[n * 20 + kb + t + 4];
            }
            #pragma unroll
            for (int mi = 0; mi < 2; mi++)
                #pragma unroll
                for (int nj = 0; nj < 8; nj++) {
                    asm volatile(
                        "mma.sync.aligned.m16n8k16.row.col.f32.f16.f16.f32 "
                        "{%0,%1,%2,%3}, {%4,%5,%6,%7}, {%8,%9}, {%0,%1,%2,%3};"
                        : "+f"(acc[mi][nj][0]), "+f"(acc[mi][nj][1]),
                          "+f"(acc[mi][nj][2]), "+f"(acc[mi][nj][3])
                        : "r"(af[mi][0]), "r"(af[mi][1]), "r"(af[mi][2]), "r"(af[mi][3]),
                          "r"(bf[nj][0]), "r"(bf[nj][1]));
                }
        }
        if (++stage == 3) stage = 0;
    }

    float bv0[8], bv1[8];
    #pragma unroll
    for (int nj = 0; nj < 8; nj++) {
        int col = ncol + nj * 8 + 2 * t;
        bv0[nj] = bias[col]; bv1[nj] = bias[col + 1];
    }

    if (EPI == 0) {
        #pragma unroll
        for (int mi = 0; mi < 2; mi++) {
            int r_lo = row0 + mrow + mi * 16 + g;
            int r_hi = r_lo + 8;
            #pragma unroll
            for (int nj = 0; nj < 8; nj++) {
                int col = ncol + nj * 8 + 2 * t;
                float2 v0, v1;
                v0.x = acc[mi][nj][0] + bv0[nj]; v0.y = acc[mi][nj][1] + bv1[nj];
                v1.x = acc[mi][nj][2] + bv0[nj]; v1.y = acc[mi][nj][3] + bv1[nj];
                if (relu) {
                    v0.x = fmaxf(v0.x, 0.f); v0.y = fmaxf(v0.y, 0.f);
                    v1.x = fmaxf(v1.x, 0.f); v1.y = fmaxf(v1.y, 0.f);
                }
                if (r_lo < NN)
                    *(__half2*)&C16[(size_t)r_lo * 128 + col] = __float22half2_rn(v0);
                if (r_hi < NN)
                    *(__half2*)&C16[(size_t)r_hi * 128 + col] = __float22half2_rn(v1);
            }
        }
    } else if (EPI == 1) {
        float S[4] = {0.f, 0.f, 0.f, 0.f}, Q[4] = {0.f, 0.f, 0.f, 0.f};
        #pragma unroll
        for (int mi = 0; mi < 2; mi++)
            #pragma unroll
            for (int nj = 0; nj < 8; nj++) {
                float a0 = acc[mi][nj][0] + bv0[nj], a1 = acc[mi][nj][1] + bv1[nj];
                float a2 = acc[mi][nj][2] + bv0[nj], a3 = acc[mi][nj][3] + bv1[nj];
                S[mi * 2]     += a0 + a1; Q[mi * 2]     += a0 * a0 + a1 * a1;
                S[mi * 2 + 1] += a2 + a3; Q[mi * 2 + 1] += a2 * a2 + a3 * a3;
            }
        #pragma unroll
        for (int ri = 0; ri < 4; ri++) {
            S[ri] += __shfl_xor_sync(0xffffffffu, S[ri], 1);
            S[ri] += __shfl_xor_sync(0xffffffffu, S[ri], 2);
            Q[ri] += __shfl_xor_sync(0xffffffffu, Q[ri], 1);
            Q[ri] += __shfl_xor_sync(0xffffffffu, Q[ri], 2);
        }
        float2* red = (float2*)smem;
        __syncthreads();
        if (t == 0) {
            #pragma unroll
            for (int ri = 0; ri < 4; ri++) {
                int row = mrow + (ri >> 1) * 16 + g + (ri & 1) * 8;
                red[row * 2 + half_id] = make_float2(S[ri], Q[ri]);
            }
        }
        __syncthreads();
        float mu[4], rs[4];
        #pragma unroll
        for (int ri = 0; ri < 4; ri++) {
            int row = mrow + (ri >> 1) * 16 + g + (ri & 1) * 8;
            float2 p0 = red[row * 2], p1 = red[row * 2 + 1];
            float Sf = p0.x + p1.x, Qf = p0.y + p1.y;
            mu[ri] = Sf * (1.0f / 128.0f);
            float var = Qf * (1.0f / 128.0f) - mu[ri] * mu[ri];
            rs[ri] = rsqrtf(var + 1e-5f);
        }
        #pragma unroll
        for (int mi = 0; mi < 2; mi++) {
            int r_lo = row0 + mrow + mi * 16 + g;
            int r_hi = r_lo + 8;
            #pragma unroll
            for (int nj = 0; nj < 8; nj++) {
                int col = ncol + nj * 8 + 2 * t;
                float g0 = q1[col], g1 = q1[col + 1];
                float e0 = q2[col], e1 = q2[col + 1];
                if (r_lo < NN) {
                    float a0 = acc[mi][nj][0] + bv0[nj], a1 = acc[mi][nj][1] + bv1[nj];
                    float o0 = fmaxf((a0 - mu[mi * 2]) * rs[mi * 2] * g0 + e0, 0.f);
                    float o1 = fmaxf((a1 - mu[mi * 2]) * rs[mi * 2] * g1 + e1, 0.f);
                    float2 r = __half22float2(*(const __half2*)&R16[(size_t)r_lo * 128 + col]);
                    *(__half2*)&C16[(size_t)r_lo * 128 + col] =
                        __float22half2_rn(make_float2(r.x + o0, r.y + o1));
                }
                if (r_hi < NN) {
                    float a2 = acc[mi][nj][2] + bv0[nj], a3 = acc[mi][nj][3] + bv1[nj];
                    float o2 = fmaxf((a2 - mu[mi * 2 + 1]) * rs[mi * 2 + 1] * g0 + e0, 0.f);
                    float o3 = fmaxf((a3 - mu[mi * 2 + 1]) * rs[mi * 2 + 1] * g1 + e1, 0.f);
                    float2 r = __half22float2(*(const __half2*)&R16[(size_t)r_hi * 128 + col]);
                    *(__half2*)&C16[(size_t)r_hi * 128 + col] =
                        __float22half2_rn(make_float2(r.x + o2, r.y + o3));
                }
            }
        }
    } else {
        float sl[4] = {0.f, 0.f, 0.f, 0.f}, sr[4] = {0.f, 0.f, 0.f, 0.f};
        #pragma unroll
        for (int nj = 0; nj < 8; nj++) {
            int col = ncol + nj * 8 + 2 * t;
            float wl0 = __ldg(&q1[col]), wl1 = __ldg(&q1[col + 1]);
            float wr0 = __ldg(&q2[col]), wr1 = __ldg(&q2[col + 1]);
            #pragma unroll
            for (int mi = 0; mi < 2; mi++) {
                float a0 = fmaxf(acc[mi][nj][0] + bv0[nj], 0.f);
                float a1 = fmaxf(acc[mi][nj][1] + bv1[nj], 0.f);
                float a2 = fmaxf(acc[mi][nj][2] + bv0[nj], 0.f);
                float a3 = fmaxf(acc[mi][nj][3] + bv1[nj], 0.f);
                sl[mi * 2]     += a0 * wl0 + a1 * wl1;
                sr[mi * 2]     += a0 * wr0 + a1 * wr1;
                sl[mi * 2 + 1] += a2 * wl0 + a3 * wl1;
                sr[mi * 2 + 1] += a2 * wr0 + a3 * wr1;
            }
        }
        #pragma unroll
        for (int ri = 0; ri < 4; ri++) {
            sl[ri] += __shfl_xor_sync(0xffffffffu, sl[ri], 1);
            sl[ri] += __shfl_xor_sync(0xffffffffu, sl[ri], 2);
            sr[ri] += __shfl_xor_sync(0xffffffffu, sr[ri], 1);
            sr[ri] += __shfl_xor_sync(0xffffffffu, sr[ri], 2);
        }
        float2* red = (float2*)smem;
        __syncthreads();
        if (t == 0) {
            #pragma unroll
            for (int ri = 0; ri < 4; ri++) {
                int row = mrow + (ri >> 1) * 16 + g + (ri & 1) * 8;
                red[row * 2 + half_id] = make_float2(sl[ri], sr[ri]);
            }
        }
        __syncthreads();
        if (t == 0 && half_id == 0) {
            #pragma unroll
            for (int ri = 0; ri < 4; ri++) {
                int row = mrow + (ri >> 1) * 16 + g + (ri & 1) * 8;
                int gr = row0 + row;
                if (gr < NN) {
                    float2 p0 = red[row * 2], p1 = red[row * 2 + 1];
                    g_zl[gr] = p0.x + p1.x;
                    g_zr[gr] = p0.y + p1.y;
                }
            }
        }
    }
}

// ---------------- final: out = zr + b4 + deginv * sum(zl[neighbors]) ----------------
__global__ void final_kernel(const float* __restrict__ b4, float* __restrict__ out) {
    int i = blockIdx.x * blockDim.x + threadIdx.x;
    if (i >= NN) return;
    int s = g_rowptr[i], e = g_rowptr[i + 1];
    float sum = 0.f;
    int j = s;
    for (; j + 8 <= e; j += 8) {
        float z0 = __ldg(&g_zl[g_csr[j]]);
        float z1 = __ldg(&g_zl[g_csr[j + 1]]);
        float z2 = __ldg(&g_zl[g_csr[j + 2]]);
        float z3 = __ldg(&g_zl[g_csr[j + 3]]);
        float z4 = __ldg(&g_zl[g_csr[j + 4]]);
        float z5 = __ldg(&g_zl[g_csr[j + 5]]);
        float z6 = __ldg(&g_zl[g_csr[j + 6]]);
        float z7 = __ldg(&g_zl[g_csr[j + 7]]);
        sum += ((z0 + z1) + (z2 + z3)) + ((z4 + z5) + (z6 + z7));
    }
    for (; j < e; j++) sum += __ldg(&g_zl[g_csr[j]]);
    out[i] = g_zr[i] + b4[0] + g_deginv[i] * sum;
}

// ---------------- host ----------------
template <typename T>
static T* sym(const void* s) {
    void* p = nullptr;
    cudaGetSymbolAddress(&p, s);
    return (T*)p;
}

extern "C" void kernel_launch(void* const* d_in, const int* in_sizes, int n_in,
                              void* d_out, int out_size) {
    const float* x    = (const float*)d_in[0];
    const int*   ei   = (const int*)d_in[1];     // int32 (JAX x64 disabled)
    const float* Wl1  = (const float*)d_in[2];
    const float* Wr1  = (const float*)d_in[3];
    const float* b1   = (const float*)d_in[4];
    const float* ln_g = (const float*)d_in[5];
    const float* ln_b = (const float*)d_in[6];
    const float* Wres = (const float*)d_in[7];
    const float* bres = (const float*)d_in[8];
    const float* Wl2  = (const float*)d_in[9];
    const float* Wr2  = (const float*)d_in[10];
    const float* b2   = (const float*)d_in[11];
    const float* Wl3  = (const float*)d_in[12];
    const float* Wr3  = (const float*)d_in[13];
    const float* b3   = (const float*)d_in[14];
    const float* Wl4  = (const float*)d_in[15];
    const float* Wr4  = (const float*)d_in[16];
    const float* b4   = (const float*)d_in[17];
    float* out = (float*)d_out;

    __half* x16   = sym<__half>(g_x16);
    __half* h16   = sym<__half>(g_h16);
    __half* t16   = sym<__half>(g_t16);
    __half* agg16 = sym<__half>(g_agg16);
    __half* wt16  = sym<__half>(g_wt16);

    static int inited = 0;
    if (!inited) {
        inited = 1;
        cudaFuncSetAttribute(gemm_tc<0>, cudaFuncAttributeMaxDynamicSharedMemorySize, GSMEM);
        cudaFuncSetAttribute(gemm_tc<1>, cudaFuncAttributeMaxDynamicSharedMemorySize, GSMEM);
        cudaFuncSetAttribute(gemm_tc<2>, cudaFuncAttributeMaxDynamicSharedMemorySize, GSMEM);
    }

    const int warpBlocks = (NN + 7) / 8;          // 12500
    const int gemmBlocks = (NN + 127) / 128;      // 782
    const int edgeBlocks = (EE + 255) / 256;
    const int nodeBlocks = (NN + 255) / 256;
    const int convBlocks = (NN * 64 + 90112 + 255) / 256;

    // CSR + fp16 pre-conversion (weights transposed), rank-producing histogram
    k_conv_count<<<convBlocks + edgeBlocks, 256>>>(x, ei, Wres, Wl1, Wr1, Wl2, Wr2,
                                                   Wl3, Wr3, convBlocks);
    k_scan1<<<NB, 1024>>>();
    // residual: t16 = x16 @ Wres^T + bres (fp16 only; t16 free until layer 2)
    gemm_tc<0><<<gemmBlocks, 256, GSMEM>>>(x16, wt16 + W_RES, nullptr, nullptr, bres,
                                           nullptr, t16, 64, 0, 0, nullptr, nullptr);
    k_scan3<<<NB, 1024>>>();
    k_fill<<<edgeBlocks, 256>>>(ei);

    // Layer 1: agg64(x16) -> agg16; h16 = t16 + relu(LN(agg@Wl1 + x16@Wr1 + b1))
    agg_kernel<64><<<warpBlocks, 256>>>(x16, agg16);
    gemm_tc<1><<<gemmBlocks, 256, GSMEM>>>(agg16, wt16 + W_L1, x16, wt16 + W_R1, b1,
                                           t16, h16, 64, 1, 0, ln_g, ln_b);

    // Layer 2: t16 = relu(agg128(h16)@Wl2 + h16@Wr2 + b2)
    agg_kernel<128><<<warpBlocks, 256>>>(h16, agg16);
    gemm_tc<0><<<gemmBlocks, 256, GSMEM>>>(agg16, wt16 + W_L2, h16, wt16 + W_R2, b2,
                                           nullptr, t16, 128, 1, 1, nullptr, nullptr);

    // Layer 3+4a: zl/zr = relu(agg128(t16)@Wl3 + t16@Wr3 + b3) . Wl4/Wr4
    agg_kernel<128><<<warpBlocks, 256>>>(t16, agg16);
    gemm_tc<2><<<gemmBlocks, 256, GSMEM>>>(agg16, wt16 + W_L3, t16, wt16 + W_R3, b3,
                                           nullptr, nullptr, 128, 1, 0, Wl4, Wr4);

    // Layer 4b
    final_kernel<<<nodeBlocks, 256>>>(b4, out);
}